// round 3
// baseline (speedup 1.0000x reference)
#include <cuda_runtime.h>
#include <cstdint>
#include <cstddef>

#define BB 256
#define TT 512
#define II 128
#define HH 256
#define GG 768

__device__ float g_xg[(size_t)BB * TT * GG];

// ---------------- f32x2 helpers ----------------
__device__ __forceinline__ unsigned long long pk2(float x, float y) {
    unsigned long long r;
    asm("mov.b64 %0, {%1, %2};" : "=l"(r) : "f"(x), "f"(y));
    return r;
}
__device__ __forceinline__ void up2(unsigned long long v, float& a, float& b) {
    asm("mov.b64 {%0, %1}, %2;" : "=f"(a), "=f"(b) : "l"(v));
}
__device__ __forceinline__ void fma2(unsigned long long& d,
                                     unsigned long long a, unsigned long long b) {
    asm("fma.rn.f32x2 %0, %1, %2, %0;" : "+l"(d) : "l"(a), "l"(b));
}
__device__ __forceinline__ unsigned long long add2(unsigned long long a,
                                                   unsigned long long b) {
    unsigned long long r;
    asm("add.rn.f32x2 %0, %1, %2;" : "=l"(r) : "l"(a), "l"(b));
    return r;
}
__device__ __forceinline__ void lds_v2b64(uint32_t addr,
                                          unsigned long long& a, unsigned long long& b) {
    asm volatile("ld.shared.v2.b64 {%0, %1}, [%2];" : "=l"(a), "=l"(b) : "r"(addr));
}
__device__ __forceinline__ unsigned long long lds_b64(uint32_t addr) {
    unsigned long long r;
    asm volatile("ld.shared.b64 %0, [%1];" : "=l"(r) : "r"(addr));
    return r;
}
__device__ __forceinline__ void sts_v2b64(uint32_t addr,
                                          unsigned long long a, unsigned long long b) {
    asm volatile("st.shared.v2.b64 [%0], {%1, %2};" :: "r"(addr), "l"(a), "l"(b) : "memory");
}

// ---------------------------------------------------------------------------
// Phase 1:  xg = x @ W_ih^T + b_ih   (M=131072, N=768, K=128)
// Full-K single stage, 3 CTAs/SM, FFMA2 inner loop.
// ---------------------------------------------------------------------------
#define SM1_BYTES (2 * 128 * 68 * 4)

__global__ __launch_bounds__(256, 3) void xg_gemm_kernel(
    const float* __restrict__ x,
    const float* __restrict__ Wih,
    const float* __restrict__ bih)
{
    extern __shared__ float sm1[];
    float (*xs)[68] = (float(*)[68])sm1;              // [128 k][68]
    float (*ws)[68] = (float(*)[68])(sm1 + 128 * 68); // [128 k][68]
    const int tid = threadIdx.x;
    const int bm = blockIdx.x;
    const int bn = blockIdx.y;
    const float* xr = x   + (size_t)bm * 64 * II;
    const float* wr = Wih + (size_t)bn * 64 * II;
    const int r0 = (tid >> 4) << 2;
    const int c0 = (tid & 15) << 2;
    const uint32_t ws_s = (uint32_t)__cvta_generic_to_shared(&ws[0][0]);

    // stage all K=128 for 64 rows of x and W (transposed to k-major)
#pragma unroll
    for (int l = 0; l < 8; ++l) {
        int f   = l * 256 + tid;
        int row = f >> 5;        // 0..63
        int kq  = f & 31;        // 0..31 (k quads)
        float4 v = *(const float4*)(xr + (size_t)row * II + kq * 4);
        xs[kq * 4 + 0][row] = v.x; xs[kq * 4 + 1][row] = v.y;
        xs[kq * 4 + 2][row] = v.z; xs[kq * 4 + 3][row] = v.w;
        float4 w = *(const float4*)(wr + (size_t)row * II + kq * 4);
        ws[kq * 4 + 0][row] = w.x; ws[kq * 4 + 1][row] = w.y;
        ws[kq * 4 + 2][row] = w.z; ws[kq * 4 + 3][row] = w.w;
    }
    __syncthreads();

    unsigned long long acc[4][2];
#pragma unroll
    for (int i = 0; i < 4; ++i) { acc[i][0] = 0ULL; acc[i][1] = 0ULL; }

#pragma unroll 8
    for (int k = 0; k < 128; ++k) {
        float4 a = *(const float4*)&xs[k][r0];
        unsigned long long b01, b23;
        lds_v2b64(ws_s + (uint32_t)(k * 68 + c0) * 4u, b01, b23);
        unsigned long long a0 = pk2(a.x, a.x);
        unsigned long long a1 = pk2(a.y, a.y);
        unsigned long long a2 = pk2(a.z, a.z);
        unsigned long long a3 = pk2(a.w, a.w);
        fma2(acc[0][0], a0, b01); fma2(acc[0][1], a0, b23);
        fma2(acc[1][0], a1, b01); fma2(acc[1][1], a1, b23);
        fma2(acc[2][0], a2, b01); fma2(acc[2][1], a2, b23);
        fma2(acc[3][0], a3, b01); fma2(acc[3][1], a3, b23);
    }

    float4 bb = *(const float4*)(bih + bn * 64 + c0);
#pragma unroll
    for (int i = 0; i < 4; ++i) {
        float4 o;
        up2(acc[i][0], o.x, o.y);
        up2(acc[i][1], o.z, o.w);
        o.x += bb.x; o.y += bb.y; o.z += bb.z; o.w += bb.w;
        *(float4*)(g_xg + (size_t)(bm * 64 + r0 + i) * GG + bn * 64 + c0) = o;
    }
}

// ---------------------------------------------------------------------------
// Phase 2: persistent recurrent kernel. 32 clusters x 4 CTAs, 768 threads.
// Thread layout: kq = tid/192 (k quarter), bh = (tid%192)/96 (batch half),
// rp = tid%96 (rows 2rp, 2rp+1). Each thread: 2 rows x 4 batches, 64 k-iters.
// ---------------------------------------------------------------------------
#define TPB2 768
// floats: wsm 256*192 | hsm 2*256*8 | ps 3*192*8 | bsm 192
#define SM2_FLOATS (256 * 192 + 2 * 256 * 8 + 3 * 192 * 8 + 192)
#define SM2_BYTES  (SM2_FLOATS * 4)

__device__ __forceinline__ void cluster_sync_() {
    asm volatile("barrier.cluster.arrive.aligned;" ::: "memory");
    asm volatile("barrier.cluster.wait.aligned;" ::: "memory");
}

__global__ __launch_bounds__(TPB2, 1) __cluster_dims__(4, 1, 1)
void gru_seq_kernel(const float* __restrict__ Whh,
                    const float* __restrict__ bhh,
                    float* __restrict__ out)
{
    extern __shared__ float smf[];
    float* wsm = smf;                       // [256 k][192 rows]
    float* hsm = wsm + 256 * 192;           // [2][256 k][8 b]
    float* ps  = hsm + 2 * 256 * 8;         // [3][192][8] partials (kq 1..3)
    float* bsm = ps + 3 * 192 * 8;          // [192]

    const int tid = threadIdx.x;
    uint32_t srank;
    asm("mov.u32 %0, %%cluster_ctarank;" : "=r"(srank));
    const int s = (int)srank;
    const int g = blockIdx.x >> 2;

    const uint32_t wsm_s = (uint32_t)__cvta_generic_to_shared(wsm);
    const uint32_t hsm_s = (uint32_t)__cvta_generic_to_shared(hsm);
    const uint32_t ps_s  = (uint32_t)__cvta_generic_to_shared(ps);

    for (int i = tid; i < 192 * 256; i += TPB2) {
        int r3 = i >> 8;
        int k  = i & 255;
        int grow = ((r3 >> 6) << 8) + (s << 6) + (r3 & 63);
        wsm[k * 192 + r3] = Whh[(size_t)grow * 256 + k];
    }
    if (tid < 192) {
        int grow = ((tid >> 6) << 8) + (s << 6) + (tid & 63);
        bsm[tid] = bhh[grow];
    }
    for (int i = tid; i < 2 * 256 * 8; i += TPB2) hsm[i] = 0.f;
    __syncthreads();
    cluster_sync_();

    const int kq = tid / 192;
    const int rem = tid % 192;
    const int bh = rem / 96;
    const int rp = rem % 96;
    const uint32_t wka = wsm_s + (uint32_t)(kq * 64 * 192 + 2 * rp) * 4u;
    const uint32_t hoff = (uint32_t)(kq * 64 * 8 + bh * 4) * 4u;

    const int jj = tid >> 2;            // gate j (tid<256): 0..63
    const int bq = (tid & 3) * 2;       // gate batch pair: 0,2,4,6

    for (int t = 0; t < TT; ++t) {
        const int p = t & 1;

        // prefetch xg for this step (consumed after the GEMM)
        float xr0, xz0, xn0, xr1, xz1, xn1;
        if (tid < 256) {
            size_t base = ((size_t)(g * 8 + bq) * TT + t) * GG + (s << 6) + jj;
            xr0 = g_xg[base];          xz0 = g_xg[base + 256];
            xn0 = g_xg[base + 512];
            xr1 = g_xg[base + (size_t)TT * GG];
            xz1 = g_xg[base + (size_t)TT * GG + 256];
            xn1 = g_xg[base + (size_t)TT * GG + 512];
        }

        // ---- GEMM: rows (2rp, 2rp+1) x 4 batches over k-quarter ----
        unsigned long long a00 = 0, a01 = 0, a10 = 0, a11 = 0;
        {
            const uint32_t ha = hsm_s + (uint32_t)(p * 2048) * 4u + hoff;
#pragma unroll 8
            for (int k = 0; k < 64; ++k) {
                unsigned long long wp_ = lds_b64(wka + (uint32_t)k * 768u);
                unsigned long long h01, h23;
                lds_v2b64(ha + (uint32_t)k * 32u, h01, h23);
                float w0, w1;
                up2(wp_, w0, w1);
                unsigned long long w0d = pk2(w0, w0);
                unsigned long long w1d = pk2(w1, w1);
                fma2(a00, h01, w0d); fma2(a01, h23, w0d);
                fma2(a10, h01, w1d); fma2(a11, h23, w1d);
            }
        }

        if (kq) {
            uint32_t d = ps_s + (uint32_t)((kq - 1) * 1536 + 2 * rp * 8 + bh * 4) * 4u;
            sts_v2b64(d,       a00, a01);
            sts_v2b64(d + 32u, a10, a11);
        }
        __syncthreads();
        if (kq == 0) {
            uint32_t base0 = ps_s + (uint32_t)(2 * rp * 8 + bh * 4) * 4u;
            unsigned long long f0 = a00, f1 = a01, g0 = a10, g1 = a11;
#pragma unroll
            for (int buf = 0; buf < 3; ++buf) {
                unsigned long long p0, p1, q0, q1;
                lds_v2b64(base0 + (uint32_t)buf * 6144u, p0, p1);
                lds_v2b64(base0 + (uint32_t)buf * 6144u + 32u, q0, q1);
                f0 = add2(f0, p0); f1 = add2(f1, p1);
                g0 = add2(g0, q0); g1 = add2(g1, q1);
            }
            float b0v = bsm[2 * rp], b1v = bsm[2 * rp + 1];
            unsigned long long b0d = pk2(b0v, b0v);
            unsigned long long b1d = pk2(b1v, b1v);
            f0 = add2(f0, b0d); f1 = add2(f1, b0d);
            g0 = add2(g0, b1d); g1 = add2(g1, b1d);
            sts_v2b64(base0,       f0, f1);
            sts_v2b64(base0 + 32u, g0, g1);
        }
        __syncthreads();

        // ---- gates: 256 threads x (1 j, 2 batches) ----
        if (tid < 256) {
            const float* hb = hsm + p * 2048;
            float2 hr = *(const float2*)(ps + jj * 8 + bq);
            float2 hz = *(const float2*)(ps + (64 + jj) * 8 + bq);
            float2 hn = *(const float2*)(ps + (128 + jj) * 8 + bq);
            float2 ho = *(const float2*)(hb + ((s << 6) + jj) * 8 + bq);

            float r0g = __fdividef(1.f, 1.f + __expf(-(xr0 + hr.x)));
            float z0g = __fdividef(1.f, 1.f + __expf(-(xz0 + hz.x)));
            float v0  = xn0 + r0g * hn.x;
            float n0  = 1.f - 2.f * __fdividef(1.f, __expf(2.f * v0) + 1.f);
            float hw0 = (1.f - z0g) * n0 + z0g * ho.x;

            float r1g = __fdividef(1.f, 1.f + __expf(-(xr1 + hr.y)));
            float z1g = __fdividef(1.f, 1.f + __expf(-(xz1 + hz.y)));
            float v1  = xn1 + r1g * hn.y;
            float n1  = 1.f - 2.f * __fdividef(1.f, __expf(2.f * v1) + 1.f);
            float hw1 = (1.f - z1g) * n1 + z1g * ho.y;

            uint32_t la = hsm_s +
                (uint32_t)((1 - p) * 2048 + ((s << 6) + jj) * 8 + bq) * 4u;
#pragma unroll
            for (int rk = 0; rk < 4; ++rk) {
                uint32_t ra;
                asm volatile("mapa.shared::cluster.u32 %0, %1, %2;"
                             : "=r"(ra) : "r"(la), "r"(rk));
                asm volatile("st.shared::cluster.v2.f32 [%0], {%1, %2};"
                             :: "r"(ra), "f"(hw0), "f"(hw1) : "memory");
            }
            size_t ob = ((size_t)(g * 8 + bq) * TT + t) * HH + (s << 6) + jj;
            out[ob] = hw0;
            out[ob + (size_t)TT * HH] = hw1;
        }
        cluster_sync_();
    }
}

// ---------------------------------------------------------------------------
extern "C" void kernel_launch(void* const* d_in, const int* in_sizes, int n_in,
                              void* d_out, int out_size)
{
    const float* x   = (const float*)d_in[0];
    const float* Wih = (const float*)d_in[1];
    const float* Whh = (const float*)d_in[2];
    const float* bih = (const float*)d_in[3];
    const float* bhh = (const float*)d_in[4];
    float* out = (float*)d_out;

    cudaFuncSetAttribute(xg_gemm_kernel,
                         cudaFuncAttributeMaxDynamicSharedMemorySize, SM1_BYTES);
    cudaFuncSetAttribute(gru_seq_kernel,
                         cudaFuncAttributeMaxDynamicSharedMemorySize, SM2_BYTES);

    dim3 g1(BB * TT / 64, GG / 64);
    xg_gemm_kernel<<<g1, 256, SM1_BYTES>>>(x, Wih, bih);
    gru_seq_kernel<<<128, TPB2, SM2_BYTES>>>(Whh, bhh, out);
}

// round 5
// speedup vs baseline: 1.2514x; 1.2514x over previous
#include <cuda_runtime.h>
#include <cstdint>
#include <cstddef>

#define BB 256
#define TT 512
#define II 128
#define HH 256
#define GG 768

__device__ float g_xg[(size_t)BB * TT * GG];

// ---------------- f32x2 helpers ----------------
__device__ __forceinline__ unsigned long long pk2(float x, float y) {
    unsigned long long r;
    asm("mov.b64 %0, {%1, %2};" : "=l"(r) : "f"(x), "f"(y));
    return r;
}
__device__ __forceinline__ void up2(unsigned long long v, float& a, float& b) {
    asm("mov.b64 {%0, %1}, %2;" : "=f"(a), "=f"(b) : "l"(v));
}
__device__ __forceinline__ void fma2(unsigned long long& d,
                                     unsigned long long a, unsigned long long b) {
    asm("fma.rn.f32x2 %0, %1, %2, %0;" : "+l"(d) : "l"(a), "l"(b));
}
__device__ __forceinline__ unsigned long long add2(unsigned long long a,
                                                   unsigned long long b) {
    unsigned long long r;
    asm("add.rn.f32x2 %0, %1, %2;" : "=l"(r) : "l"(a), "l"(b));
    return r;
}
__device__ __forceinline__ void lds_v2b64(uint32_t addr,
                                          unsigned long long& a, unsigned long long& b) {
    asm volatile("ld.shared.v2.b64 {%0, %1}, [%2];" : "=l"(a), "=l"(b) : "r"(addr));
}
__device__ __forceinline__ unsigned long long lds_b64(uint32_t addr) {
    unsigned long long r;
    asm volatile("ld.shared.b64 %0, [%1];" : "=l"(r) : "r"(addr));
    return r;
}
__device__ __forceinline__ void sts_v2b64(uint32_t addr,
                                          unsigned long long a, unsigned long long b) {
    asm volatile("st.shared.v2.b64 [%0], {%1, %2};" :: "r"(addr), "l"(a), "l"(b) : "memory");
}

// ---------------------------------------------------------------------------
// Phase 1 (Round-2 version, known-good):  xg = x @ W_ih^T + b_ih
// ---------------------------------------------------------------------------
__global__ __launch_bounds__(256) void xg_gemm_kernel(
    const float* __restrict__ x,
    const float* __restrict__ Wih,
    const float* __restrict__ bih)
{
    __shared__ float xs[64][68];
    __shared__ float ws[64][68];
    const int tid = threadIdx.x;
    const int bm = blockIdx.x;
    const int bn = blockIdx.y;
    const float* xr = x   + (size_t)bm * 64 * II;
    const float* wr = Wih + (size_t)bn * 64 * II;
    const int r0 = (tid >> 4) << 2;
    const int c0 = (tid & 15) << 2;
    const uint32_t ws_s = (uint32_t)__cvta_generic_to_shared(&ws[0][0]);

    unsigned long long acc[4][2];
#pragma unroll
    for (int i = 0; i < 4; ++i) { acc[i][0] = 0ULL; acc[i][1] = 0ULL; }

    for (int kt = 0; kt < 2; ++kt) {
#pragma unroll
        for (int l = 0; l < 4; ++l) {
            int f   = l * 256 + tid;
            int row = f >> 4;
            int kq  = f & 15;
            float4 v = *(const float4*)(xr + (size_t)row * II + kt * 64 + kq * 4);
            xs[kq * 4 + 0][row] = v.x; xs[kq * 4 + 1][row] = v.y;
            xs[kq * 4 + 2][row] = v.z; xs[kq * 4 + 3][row] = v.w;
            float4 w = *(const float4*)(wr + (size_t)row * II + kt * 64 + kq * 4);
            ws[kq * 4 + 0][row] = w.x; ws[kq * 4 + 1][row] = w.y;
            ws[kq * 4 + 2][row] = w.z; ws[kq * 4 + 3][row] = w.w;
        }
        __syncthreads();
#pragma unroll 8
        for (int k = 0; k < 64; ++k) {
            float4 a = *(const float4*)&xs[k][r0];
            unsigned long long b01, b23;
            lds_v2b64(ws_s + (uint32_t)(k * 68 + c0) * 4u, b01, b23);
            unsigned long long a0 = pk2(a.x, a.x);
            unsigned long long a1 = pk2(a.y, a.y);
            unsigned long long a2 = pk2(a.z, a.z);
            unsigned long long a3 = pk2(a.w, a.w);
            fma2(acc[0][0], a0, b01); fma2(acc[0][1], a0, b23);
            fma2(acc[1][0], a1, b01); fma2(acc[1][1], a1, b23);
            fma2(acc[2][0], a2, b01); fma2(acc[2][1], a2, b23);
            fma2(acc[3][0], a3, b01); fma2(acc[3][1], a3, b23);
        }
        __syncthreads();
    }

    float4 bb = *(const float4*)(bih + bn * 64 + c0);
#pragma unroll
    for (int i = 0; i < 4; ++i) {
        float4 o;
        up2(acc[i][0], o.x, o.y);
        up2(acc[i][1], o.z, o.w);
        o.x += bb.x; o.y += bb.y; o.z += bb.z; o.w += bb.w;
        *(float4*)(g_xg + (size_t)(bm * 64 + r0 + i) * GG + bn * 64 + c0) = o;
    }
}

// ---------------------------------------------------------------------------
// Phase 2: persistent recurrent kernel. 32 clusters x 4 CTAs, 384 threads.
//
// k-PERMUTED layout: storage slot k' holds physical k = (k' + (s+1)*64) mod 256,
// so this CTA's OWN hidden slice lives at k' in [192,256). Thread kq = tid/96
// owns k' residue class kq mod 4. Per step:
//   [xg prefetch] -> cluster WAIT -> GEMM-B (k' < 192, peer slices) ->
//   deposit/reduce -> gates -> push (DSMEM) -> syncthreads -> cluster ARRIVE ->
//   GEMM-A for t+1 (own k' >= 192, no barrier needed).
// Each thread: rows (2rp, 2rp+1) x 8 batches = 8 f32x2 accumulators.
// ---------------------------------------------------------------------------
#define TPB2 384
// floats: wsm 256*192 | hsm 2*256*8 | ps 3*192*8 | bsm 192
#define SM2_FLOATS (256 * 192 + 2 * 256 * 8 + 3 * 192 * 8 + 192)
#define SM2_BYTES  (SM2_FLOATS * 4)

__global__ __launch_bounds__(TPB2, 1) __cluster_dims__(4, 1, 1)
void gru_seq_kernel(const float* __restrict__ Whh,
                    const float* __restrict__ bhh,
                    float* __restrict__ out)
{
    extern __shared__ float smf[];
    float* wsm = smf;                       // [256 k'][192 rows]
    float* hsm = wsm + 256 * 192;           // [2][256 k'][8 b]
    float* ps  = hsm + 2 * 256 * 8;         // [3][192 rows][8 b] partials
    float* bsm = ps + 3 * 192 * 8;          // [192]

    const int tid = threadIdx.x;
    uint32_t srank;
    asm("mov.u32 %0, %%cluster_ctarank;" : "=r"(srank));
    const int s = (int)srank;
    const int g = blockIdx.x >> 2;

    const uint32_t wsm_s = (uint32_t)__cvta_generic_to_shared(wsm);
    const uint32_t hsm_s = (uint32_t)__cvta_generic_to_shared(hsm);
    const uint32_t ps_s  = (uint32_t)__cvta_generic_to_shared(ps);

    // load W slice with per-CTA k permutation: slot k' <- phys k
    for (int i = tid; i < 192 * 256; i += TPB2) {
        int r3 = i >> 8;
        int kp = i & 255;
        int k  = (kp + ((s + 1) << 6)) & 255;
        int grow = ((r3 >> 6) << 8) + (s << 6) + (r3 & 63);
        wsm[kp * 192 + r3] = Whh[(size_t)grow * 256 + k];
    }
    if (tid < 192) {
        int grow = ((tid >> 6) << 8) + (s << 6) + (tid & 63);
        bsm[tid] = bhh[grow];
    }
    for (int i = tid; i < 2 * 256 * 8; i += TPB2) hsm[i] = 0.f;
    __syncthreads();
    asm volatile("barrier.cluster.arrive.aligned;" ::: "memory");
    asm volatile("barrier.cluster.wait.aligned;" ::: "memory");

    const int kq = tid / 96;            // k' residue class
    const int rp = tid % 96;            // rows (2rp, 2rp+1)
    const uint32_t wbase = wsm_s + (uint32_t)(2 * rp) * 4u;

    const int jj = tid >> 2;            // gate j (tid<256)
    const int bq = (tid & 3) * 2;       // gate batch pair base

    // 8 accumulators: row0 b0-7 (a00..a03), row1 b0-7 (a10..a13)
    unsigned long long a00 = 0, a01 = 0, a02 = 0, a03 = 0;
    unsigned long long a10 = 0, a11 = 0, a12 = 0, a13 = 0;

    for (int t = 0; t < TT; ++t) {
        const int p = t & 1;

        // prefetch xg(t) before the cluster wait
        float xr0, xz0, xn0, xr1, xz1, xn1;
        if (tid < 256) {
            size_t base = ((size_t)(g * 8 + bq) * TT + t) * GG + (s << 6) + jj;
            xr0 = g_xg[base];          xz0 = g_xg[base + 256];
            xn0 = g_xg[base + 512];
            xr1 = g_xg[base + (size_t)TT * GG];
            xz1 = g_xg[base + (size_t)TT * GG + 256];
            xn1 = g_xg[base + (size_t)TT * GG + 512];
        }

        if (t) asm volatile("barrier.cluster.wait.aligned;" ::: "memory");

        // ---- GEMM-B: peer k' = kq + 4i, i = 0..47 ----
        {
            uint32_t wa = wbase + (uint32_t)kq * 768u;
            uint32_t ha = hsm_s + (uint32_t)p * 8192u + (uint32_t)kq * 32u;
#pragma unroll 8
            for (int i = 0; i < 48; ++i) {
                unsigned long long wp_ = lds_b64(wa + (uint32_t)i * 3072u);
                unsigned long long h01, h23, h45, h67;
                lds_v2b64(ha + (uint32_t)i * 128u, h01, h23);
                lds_v2b64(ha + (uint32_t)i * 128u + 16u, h45, h67);
                float w0, w1;
                up2(wp_, w0, w1);
                unsigned long long w0d = pk2(w0, w0);
                unsigned long long w1d = pk2(w1, w1);
                fma2(a00, h01, w0d); fma2(a01, h23, w0d);
                fma2(a02, h45, w0d); fma2(a03, h67, w0d);
                fma2(a10, h01, w1d); fma2(a11, h23, w1d);
                fma2(a12, h45, w1d); fma2(a13, h67, w1d);
            }
        }

        if (kq) {   // deposit partials: 2 rows x 32B each
            uint32_t d = ps_s + (uint32_t)((kq - 1) * 6144 + 2 * rp * 32);
            sts_v2b64(d,       a00, a01);
            sts_v2b64(d + 16u, a02, a03);
            sts_v2b64(d + 32u, a10, a11);
            sts_v2b64(d + 48u, a12, a13);
        }
        __syncthreads();
        if (kq == 0) {  // reduce 3 partial bufs + bias -> ps[0]
            uint32_t b0a = ps_s + (uint32_t)(2 * rp * 32);
            unsigned long long f0 = a00, f1 = a01, f2 = a02, f3 = a03;
            unsigned long long e0 = a10, e1 = a11, e2 = a12, e3 = a13;
#pragma unroll
            for (int buf = 0; buf < 3; ++buf) {
                unsigned long long p0, p1, p2, p3, q0, q1, q2, q3;
                uint32_t a = b0a + (uint32_t)buf * 6144u;
                lds_v2b64(a,       p0, p1);
                lds_v2b64(a + 16u, p2, p3);
                lds_v2b64(a + 32u, q0, q1);
                lds_v2b64(a + 48u, q2, q3);
                f0 = add2(f0, p0); f1 = add2(f1, p1);
                f2 = add2(f2, p2); f3 = add2(f3, p3);
                e0 = add2(e0, q0); e1 = add2(e1, q1);
                e2 = add2(e2, q2); e3 = add2(e3, q3);
            }
            float b0v = bsm[2 * rp], b1v = bsm[2 * rp + 1];
            unsigned long long b0d = pk2(b0v, b0v);
            unsigned long long b1d = pk2(b1v, b1v);
            f0 = add2(f0, b0d); f1 = add2(f1, b0d);
            f2 = add2(f2, b0d); f3 = add2(f3, b0d);
            e0 = add2(e0, b1d); e1 = add2(e1, b1d);
            e2 = add2(e2, b1d); e3 = add2(e3, b1d);
            sts_v2b64(b0a,       f0, f1);
            sts_v2b64(b0a + 16u, f2, f3);
            sts_v2b64(b0a + 32u, e0, e1);
            sts_v2b64(b0a + 48u, e2, e3);
        }
        __syncthreads();

        // ---- gates: 256 threads x (1 j, 2 batches) ----
        if (tid < 256) {
            float2 hr = *(const float2*)(ps + jj * 8 + bq);
            float2 hz = *(const float2*)(ps + (64 + jj) * 8 + bq);
            float2 hn = *(const float2*)(ps + (128 + jj) * 8 + bq);
            float2 ho = *(const float2*)(hsm + p * 2048 + (192 + jj) * 8 + bq);

            float r0g = __fdividef(1.f, 1.f + __expf(-(xr0 + hr.x)));
            float z0g = __fdividef(1.f, 1.f + __expf(-(xz0 + hz.x)));
            float v0  = xn0 + r0g * hn.x;
            float n0  = 1.f - 2.f * __fdividef(1.f, __expf(2.f * v0) + 1.f);
            float hw0 = (1.f - z0g) * n0 + z0g * ho.x;

            float r1g = __fdividef(1.f, 1.f + __expf(-(xr1 + hr.y)));
            float z1g = __fdividef(1.f, 1.f + __expf(-(xz1 + hz.y)));
            float v1  = xn1 + r1g * hn.y;
            float n1  = 1.f - 2.f * __fdividef(1.f, __expf(2.f * v1) + 1.f);
            float hw1 = (1.f - z1g) * n1 + z1g * ho.y;

            // push to every rank at that rank's permuted slot
#pragma unroll
            for (int rk = 0; rk < 4; ++rk) {
                int slot = (((s - rk - 1) & 3) << 6) + jj;
                uint32_t la = hsm_s +
                    (uint32_t)((1 - p) * 2048 + slot * 8 + bq) * 4u;
                uint32_t ra;
                asm volatile("mapa.shared::cluster.u32 %0, %1, %2;"
                             : "=r"(ra) : "r"(la), "r"(rk));
                asm volatile("st.shared::cluster.v2.f32 [%0], {%1, %2};"
                             :: "r"(ra), "f"(hw0), "f"(hw1) : "memory");
            }
            size_t ob = ((size_t)(g * 8 + bq) * TT + t) * HH + (s << 6) + jj;
            out[ob] = hw0;
            out[ob + (size_t)TT * HH] = hw1;
        }
        __syncthreads();                 // own-slot pushes visible CTA-locally
        asm volatile("barrier.cluster.arrive.aligned;" ::: "memory");

        // ---- GEMM-A for t+1: OWN k' = 192 + kq + 4i (no barrier needed) ----
        a00 = 0; a01 = 0; a02 = 0; a03 = 0;
        a10 = 0; a11 = 0; a12 = 0; a13 = 0;
        if (t + 1 < TT) {
            uint32_t wa = wbase + (uint32_t)(192 + kq) * 768u;
            uint32_t ha = hsm_s + (uint32_t)(1 - p) * 8192u
                                + (uint32_t)(192 + kq) * 32u;
#pragma unroll 8
            for (int i = 0; i < 16; ++i) {
                unsigned long long wp_ = lds_b64(wa + (uint32_t)i * 3072u);
                unsigned long long h01, h23, h45, h67;
                lds_v2b64(ha + (uint32_t)i * 128u, h01, h23);
                lds_v2b64(ha + (uint32_t)i * 128u + 16u, h45, h67);
                float w0, w1;
                up2(wp_, w0, w1);
                unsigned long long w0d = pk2(w0, w0);
                unsigned long long w1d = pk2(w1, w1);
                fma2(a00, h01, w0d); fma2(a01, h23, w0d);
                fma2(a02, h45, w0d); fma2(a03, h67, w0d);
                fma2(a10, h01, w1d); fma2(a11, h23, w1d);
                fma2(a12, h45, w1d); fma2(a13, h67, w1d);
            }
        }
    }
    asm volatile("barrier.cluster.wait.aligned;" ::: "memory");
}

// ---------------------------------------------------------------------------
extern "C" void kernel_launch(void* const* d_in, const int* in_sizes, int n_in,
                              void* d_out, int out_size)
{
    const float* x   = (const float*)d_in[0];
    const float* Wih = (const float*)d_in[1];
    const float* Whh = (const float*)d_in[2];
    const float* bih = (const float*)d_in[3];
    const float* bhh = (const float*)d_in[4];
    float* out = (float*)d_out;

    cudaFuncSetAttribute(gru_seq_kernel,
                         cudaFuncAttributeMaxDynamicSharedMemorySize, SM2_BYTES);

    dim3 g1(BB * TT / 64, GG / 64);
    xg_gemm_kernel<<<g1, 256>>>(x, Wih, bih);
    gru_seq_kernel<<<128, TPB2, SM2_BYTES>>>(Whh, bhh, out);
}

// round 6
// speedup vs baseline: 1.3483x; 1.0775x over previous
#include <cuda_runtime.h>
#include <cstdint>
#include <cstddef>

#define BB 256
#define TT 512
#define II 128
#define HH 256
#define GG 768

typedef unsigned long long u64;

__device__ float g_xg[(size_t)BB * TT * GG];

// ---------------- f32x2 helpers (pure asm, NON-volatile => schedulable) ----
__device__ __forceinline__ u64 pk2(float x, float y) {
    u64 r;
    asm("mov.b64 %0, {%1, %2};" : "=l"(r) : "f"(x), "f"(y));
    return r;
}
__device__ __forceinline__ void up2(u64 v, float& a, float& b) {
    asm("mov.b64 {%0, %1}, %2;" : "=f"(a), "=f"(b) : "l"(v));
}
__device__ __forceinline__ void fma2(u64& d, u64 a, u64 b) {
    asm("fma.rn.f32x2 %0, %1, %2, %0;" : "+l"(d) : "l"(a), "l"(b));
}
__device__ __forceinline__ u64 add2(u64 a, u64 b) {
    u64 r;
    asm("add.rn.f32x2 %0, %1, %2;" : "=l"(r) : "l"(a), "l"(b));
    return r;
}

// ---------------------------------------------------------------------------
// Phase 1:  xg = x @ W_ih^T + b_ih   (M=131072, N=768, K=128)
// 64x64 tiles, conflict-free swizzled k-major staging, stage-1 LDG prefetch,
// compiler-visible loads, FFMA2 inner loop.
// ---------------------------------------------------------------------------
__global__ __launch_bounds__(256) void xg_gemm_kernel(
    const float* __restrict__ x,
    const float* __restrict__ Wih,
    const float* __restrict__ bih)
{
    __shared__ float xs[64][68];
    __shared__ float ws[64][68];
    const int tid = threadIdx.x;
    const int bm = blockIdx.x;
    const int bn = blockIdx.y;
    const float* xr = x   + (size_t)bm * 64 * II;
    const float* wr = Wih + (size_t)bn * 64 * II;
    const int r0 = (tid >> 4) << 2;
    const int c0 = (tid & 15) << 2;

    // staging indices: f = l*256 + tid; row = f>>4 (0..63), kq = f&15
    const int srow = tid >> 4;          // rows srow, srow+16, +32, +48 over l
    const int skq  = tid & 15;
    const int ssw  = (skq & 7) << 2;    // row swizzle for this thread's K group

    float4 xv[4], wv[4];

    // ---- load stage 0 ----
#pragma unroll
    for (int l = 0; l < 4; ++l) {
        int row = srow + l * 16;
        xv[l] = *(const float4*)(xr + (size_t)row * II + skq * 4);
        wv[l] = *(const float4*)(wr + (size_t)row * II + skq * 4);
    }
    // store stage 0 (swizzled rows: conflict-free)
#pragma unroll
    for (int l = 0; l < 4; ++l) {
        int row = (srow + l * 16) ^ ssw;
        xs[skq * 4 + 0][row] = xv[l].x; xs[skq * 4 + 1][row] = xv[l].y;
        xs[skq * 4 + 2][row] = xv[l].z; xs[skq * 4 + 3][row] = xv[l].w;
        ws[skq * 4 + 0][row] = wv[l].x; ws[skq * 4 + 1][row] = wv[l].y;
        ws[skq * 4 + 2][row] = wv[l].z; ws[skq * 4 + 3][row] = wv[l].w;
    }
    // ---- prefetch stage 1 (LDG latency hidden under compute 0) ----
#pragma unroll
    for (int l = 0; l < 4; ++l) {
        int row = srow + l * 16;
        xv[l] = *(const float4*)(xr + (size_t)row * II + 64 + skq * 4);
        wv[l] = *(const float4*)(wr + (size_t)row * II + 64 + skq * 4);
    }
    __syncthreads();

    u64 acc[4][2];
#pragma unroll
    for (int i = 0; i < 4; ++i) { acc[i][0] = 0ULL; acc[i][1] = 0ULL; }

    // ---- compute stage 0 ----
#pragma unroll 4
    for (int kk = 0; kk < 16; ++kk) {
        int sw  = (kk & 7) << 2;
        int r0s = r0 ^ sw;
        int c0s = c0 ^ sw;
#pragma unroll
        for (int j = 0; j < 4; ++j) {
            int k = kk * 4 + j;
            float4 a = *(const float4*)&xs[k][r0s];
            ulonglong2 b = *(const ulonglong2*)&ws[k][c0s];
            u64 a0 = pk2(a.x, a.x), a1 = pk2(a.y, a.y);
            u64 a2 = pk2(a.z, a.z), a3 = pk2(a.w, a.w);
            fma2(acc[0][0], a0, b.x); fma2(acc[0][1], a0, b.y);
            fma2(acc[1][0], a1, b.x); fma2(acc[1][1], a1, b.y);
            fma2(acc[2][0], a2, b.x); fma2(acc[2][1], a2, b.y);
            fma2(acc[3][0], a3, b.x); fma2(acc[3][1], a3, b.y);
        }
    }
    __syncthreads();

    // ---- store + compute stage 1 ----
#pragma unroll
    for (int l = 0; l < 4; ++l) {
        int row = (srow + l * 16) ^ ssw;
        xs[skq * 4 + 0][row] = xv[l].x; xs[skq * 4 + 1][row] = xv[l].y;
        xs[skq * 4 + 2][row] = xv[l].z; xs[skq * 4 + 3][row] = xv[l].w;
        ws[skq * 4 + 0][row] = wv[l].x; ws[skq * 4 + 1][row] = wv[l].y;
        ws[skq * 4 + 2][row] = wv[l].z; ws[skq * 4 + 3][row] = wv[l].w;
    }
    __syncthreads();
#pragma unroll 4
    for (int kk = 0; kk < 16; ++kk) {
        int sw  = (kk & 7) << 2;
        int r0s = r0 ^ sw;
        int c0s = c0 ^ sw;
#pragma unroll
        for (int j = 0; j < 4; ++j) {
            int k = kk * 4 + j;
            float4 a = *(const float4*)&xs[k][r0s];
            ulonglong2 b = *(const ulonglong2*)&ws[k][c0s];
            u64 a0 = pk2(a.x, a.x), a1 = pk2(a.y, a.y);
            u64 a2 = pk2(a.z, a.z), a3 = pk2(a.w, a.w);
            fma2(acc[0][0], a0, b.x); fma2(acc[0][1], a0, b.y);
            fma2(acc[1][0], a1, b.x); fma2(acc[1][1], a1, b.y);
            fma2(acc[2][0], a2, b.x); fma2(acc[2][1], a2, b.y);
            fma2(acc[3][0], a3, b.x); fma2(acc[3][1], a3, b.y);
        }
    }

    float4 bb = *(const float4*)(bih + bn * 64 + c0);
#pragma unroll
    for (int i = 0; i < 4; ++i) {
        float4 o;
        up2(acc[i][0], o.x, o.y);
        up2(acc[i][1], o.z, o.w);
        o.x += bb.x; o.y += bb.y; o.z += bb.z; o.w += bb.w;
        *(float4*)(g_xg + (size_t)(bm * 64 + r0 + i) * GG + bn * 64 + c0) = o;
    }
}

// ---------------------------------------------------------------------------
// Phase 2: persistent recurrent kernel. 32 clusters x 4 CTAs, 384 threads.
// R2's proven step structure (single cluster barrier), FFMA2 GEMM with
// compiler-visible loads: 4 kq (64 k each) x 96 rp (rows 2rp, 2rp+1) x 8 b.
// ---------------------------------------------------------------------------
#define TPB2 384
// floats: wsm 256*192 | hsm 2*256*8 | ps 3*192*8 | bsm 192
#define SM2_FLOATS (256 * 192 + 2 * 256 * 8 + 3 * 192 * 8 + 192)
#define SM2_BYTES  (SM2_FLOATS * 4)

__global__ __launch_bounds__(TPB2, 1) __cluster_dims__(4, 1, 1)
void gru_seq_kernel(const float* __restrict__ Whh,
                    const float* __restrict__ bhh,
                    float* __restrict__ out)
{
    extern __shared__ float smf[];
    float* wsm = smf;                       // [256 k][192 rows]
    float* hsm = wsm + 256 * 192;           // [2][256 k][8 b]
    float* ps  = hsm + 2 * 256 * 8;         // [3][192 rows][8 b] partials
    float* bsm = ps + 3 * 192 * 8;          // [192]

    const int tid = threadIdx.x;
    uint32_t srank;
    asm("mov.u32 %0, %%cluster_ctarank;" : "=r"(srank));
    const int s = (int)srank;
    const int g = blockIdx.x >> 2;

    const uint32_t hsm_s = (uint32_t)__cvta_generic_to_shared(hsm);

    // load W slice k-major: wsm[k][r3] = Whh[grow(r3)][k]
    for (int i = tid; i < 192 * 256; i += TPB2) {
        int r3 = i >> 8;
        int k  = i & 255;
        int grow = ((r3 >> 6) << 8) + (s << 6) + (r3 & 63);
        wsm[k * 192 + r3] = Whh[(size_t)grow * 256 + k];
    }
    if (tid < 192) {
        int grow = ((tid >> 6) << 8) + (s << 6) + (tid & 63);
        bsm[tid] = bhh[grow];
    }
    for (int i = tid; i < 2 * 256 * 8; i += TPB2) hsm[i] = 0.f;
    __syncthreads();
    asm volatile("barrier.cluster.arrive.aligned;" ::: "memory");
    asm volatile("barrier.cluster.wait.aligned;" ::: "memory");

    const int kq = tid / 96;            // k-quarter: k in [64*kq, 64*kq+64)
    const int rp = tid % 96;            // rows (2rp, 2rp+1)
    const float* wp = wsm + kq * 64 * 192 + 2 * rp;

    const int jj = tid >> 2;            // gate j (tid<256)
    const int bq = (tid & 3) * 2;       // gate batch pair base

    for (int t = 0; t < TT; ++t) {
        const int p = t & 1;
        const float* hp = hsm + p * 2048 + kq * 64 * 8;

        // prefetch xg(t) (global; hidden under GEMM)
        float xr0, xz0, xn0, xr1, xz1, xn1;
        if (tid < 256) {
            size_t base = ((size_t)(g * 8 + bq) * TT + t) * GG + (s << 6) + jj;
            xr0 = g_xg[base];          xz0 = g_xg[base + 256];
            xn0 = g_xg[base + 512];
            xr1 = g_xg[base + (size_t)TT * GG];
            xz1 = g_xg[base + (size_t)TT * GG + 256];
            xn1 = g_xg[base + (size_t)TT * GG + 512];
        }

        // ---- GEMM: rows (2rp, 2rp+1) x 8 batches over this k-quarter ----
        u64 a00 = 0, a01 = 0, a02 = 0, a03 = 0;
        u64 a10 = 0, a11 = 0, a12 = 0, a13 = 0;
#pragma unroll 8
        for (int k = 0; k < 64; ++k) {
            u64 wpair = *(const u64*)(wp + k * 192);
            ulonglong2 hA = *(const ulonglong2*)(hp + k * 8);
            ulonglong2 hB = *(const ulonglong2*)(hp + k * 8 + 4);
            float w0, w1;
            up2(wpair, w0, w1);
            u64 w0d = pk2(w0, w0);
            u64 w1d = pk2(w1, w1);
            fma2(a00, hA.x, w0d); fma2(a01, hA.y, w0d);
            fma2(a02, hB.x, w0d); fma2(a03, hB.y, w0d);
            fma2(a10, hA.x, w1d); fma2(a11, hA.y, w1d);
            fma2(a12, hB.x, w1d); fma2(a13, hB.y, w1d);
        }

        if (kq) {   // kq 1..3 deposit partials: 2 rows x 32B
            u64* d = (u64*)(ps + (kq - 1) * 1536 + 2 * rp * 8);
            ((ulonglong2*)d)[0] = make_ulonglong2(a00, a01);
            ((ulonglong2*)d)[1] = make_ulonglong2(a02, a03);
            ((ulonglong2*)d)[2] = make_ulonglong2(a10, a11);
            ((ulonglong2*)d)[3] = make_ulonglong2(a12, a13);
        }
        __syncthreads();
        if (kq == 0) {  // reduce 3 partial bufs + bias -> ps[0]
            float* b0 = ps + 2 * rp * 8;
#pragma unroll
            for (int buf = 0; buf < 3; ++buf) {
                const ulonglong2* a = (const ulonglong2*)(b0 + buf * 1536);
                ulonglong2 v0 = a[0], v1 = a[1], v2 = a[2], v3 = a[3];
                a00 = add2(a00, v0.x); a01 = add2(a01, v0.y);
                a02 = add2(a02, v1.x); a03 = add2(a03, v1.y);
                a10 = add2(a10, v2.x); a11 = add2(a11, v2.y);
                a12 = add2(a12, v3.x); a13 = add2(a13, v3.y);
            }
            float b0v = bsm[2 * rp], b1v = bsm[2 * rp + 1];
            u64 b0d = pk2(b0v, b0v);
            u64 b1d = pk2(b1v, b1v);
            a00 = add2(a00, b0d); a01 = add2(a01, b0d);
            a02 = add2(a02, b0d); a03 = add2(a03, b0d);
            a10 = add2(a10, b1d); a11 = add2(a11, b1d);
            a12 = add2(a12, b1d); a13 = add2(a13, b1d);
            ulonglong2* d = (ulonglong2*)b0;
            d[0] = make_ulonglong2(a00, a01);
            d[1] = make_ulonglong2(a02, a03);
            d[2] = make_ulonglong2(a10, a11);
            d[3] = make_ulonglong2(a12, a13);
        }
        __syncthreads();

        // ---- gates: 256 threads x (1 j, 2 batches) ----
        if (tid < 256) {
            float2 hr = *(const float2*)(ps + jj * 8 + bq);
            float2 hz = *(const float2*)(ps + (64 + jj) * 8 + bq);
            float2 hn = *(const float2*)(ps + (128 + jj) * 8 + bq);
            float2 ho = *(const float2*)(hsm + p * 2048 + ((s << 6) + jj) * 8 + bq);

            float r0g = __fdividef(1.f, 1.f + __expf(-(xr0 + hr.x)));
            float z0g = __fdividef(1.f, 1.f + __expf(-(xz0 + hz.x)));
            float v0  = xn0 + r0g * hn.x;
            float n0  = 1.f - 2.f * __fdividef(1.f, __expf(2.f * v0) + 1.f);
            float hw0 = (1.f - z0g) * n0 + z0g * ho.x;

            float r1g = __fdividef(1.f, 1.f + __expf(-(xr1 + hr.y)));
            float z1g = __fdividef(1.f, 1.f + __expf(-(xz1 + hz.y)));
            float v1  = xn1 + r1g * hn.y;
            float n1  = 1.f - 2.f * __fdividef(1.f, __expf(2.f * v1) + 1.f);
            float hw1 = (1.f - z1g) * n1 + z1g * ho.y;

            uint32_t la = hsm_s +
                (uint32_t)((1 - p) * 2048 + ((s << 6) + jj) * 8 + bq) * 4u;
#pragma unroll
            for (int rk = 0; rk < 4; ++rk) {
                uint32_t ra;
                asm volatile("mapa.shared::cluster.u32 %0, %1, %2;"
                             : "=r"(ra) : "r"(la), "r"(rk));
                asm volatile("st.shared::cluster.v2.f32 [%0], {%1, %2};"
                             :: "r"(ra), "f"(hw0), "f"(hw1) : "memory");
            }
            size_t ob = ((size_t)(g * 8 + bq) * TT + t) * HH + (s << 6) + jj;
            out[ob] = hw0;
            out[ob + (size_t)TT * HH] = hw1;
        }
        asm volatile("barrier.cluster.arrive.aligned;" ::: "memory");
        asm volatile("barrier.cluster.wait.aligned;" ::: "memory");
    }
}

// ---------------------------------------------------------------------------
extern "C" void kernel_launch(void* const* d_in, const int* in_sizes, int n_in,
                              void* d_out, int out_size)
{
    const float* x   = (const float*)d_in[0];
    const float* Wih = (const float*)d_in[1];
    const float* Whh = (const float*)d_in[2];
    const float* bih = (const float*)d_in[3];
    const float* bhh = (const float*)d_in[4];
    float* out = (float*)d_out;

    cudaFuncSetAttribute(gru_seq_kernel,
                         cudaFuncAttributeMaxDynamicSharedMemorySize, SM2_BYTES);

    dim3 g1(BB * TT / 64, GG / 64);
    xg_gemm_kernel<<<g1, 256>>>(x, Wih, bih);
    gru_seq_kernel<<<128, TPB2, SM2_BYTES>>>(Whh, bhh, out);
}

// round 8
// speedup vs baseline: 1.9525x; 1.4481x over previous
#include <cuda_runtime.h>
#include <cuda_bf16.h>
#include <cstdint>
#include <cstddef>

#define BB 256
#define TT 512
#define II 128
#define HH 256
#define GG 768

typedef unsigned long long u64;

__device__ float g_xg[(size_t)BB * TT * GG];

// ---------------- f32x2 helpers (phase 1) ----------------
__device__ __forceinline__ u64 pk2(float x, float y) {
    u64 r;
    asm("mov.b64 %0, {%1, %2};" : "=l"(r) : "f"(x), "f"(y));
    return r;
}
__device__ __forceinline__ void up2(u64 v, float& a, float& b) {
    asm("mov.b64 {%0, %1}, %2;" : "=f"(a), "=f"(b) : "l"(v));
}
__device__ __forceinline__ void fma2(u64& d, u64 a, u64 b) {
    asm("fma.rn.f32x2 %0, %1, %2, %0;" : "+l"(d) : "l"(a), "l"(b));
}

// ---------------------------------------------------------------------------
// Phase 1 (R6 version, known-good ~645us): xg = x @ W_ih^T + b_ih
// ---------------------------------------------------------------------------
__global__ __launch_bounds__(256) void xg_gemm_kernel(
    const float* __restrict__ x,
    const float* __restrict__ Wih,
    const float* __restrict__ bih)
{
    __shared__ float xs[64][68];
    __shared__ float ws[64][68];
    const int tid = threadIdx.x;
    const int bm = blockIdx.x;
    const int bn = blockIdx.y;
    const float* xr = x   + (size_t)bm * 64 * II;
    const float* wr = Wih + (size_t)bn * 64 * II;
    const int r0 = (tid >> 4) << 2;
    const int c0 = (tid & 15) << 2;

    const int srow = tid >> 4;
    const int skq  = tid & 15;
    const int ssw  = (skq & 7) << 2;

    float4 xv[4], wv[4];
#pragma unroll
    for (int l = 0; l < 4; ++l) {
        int row = srow + l * 16;
        xv[l] = *(const float4*)(xr + (size_t)row * II + skq * 4);
        wv[l] = *(const float4*)(wr + (size_t)row * II + skq * 4);
    }
#pragma unroll
    for (int l = 0; l < 4; ++l) {
        int row = (srow + l * 16) ^ ssw;
        xs[skq * 4 + 0][row] = xv[l].x; xs[skq * 4 + 1][row] = xv[l].y;
        xs[skq * 4 + 2][row] = xv[l].z; xs[skq * 4 + 3][row] = xv[l].w;
        ws[skq * 4 + 0][row] = wv[l].x; ws[skq * 4 + 1][row] = wv[l].y;
        ws[skq * 4 + 2][row] = wv[l].z; ws[skq * 4 + 3][row] = wv[l].w;
    }
#pragma unroll
    for (int l = 0; l < 4; ++l) {
        int row = srow + l * 16;
        xv[l] = *(const float4*)(xr + (size_t)row * II + 64 + skq * 4);
        wv[l] = *(const float4*)(wr + (size_t)row * II + 64 + skq * 4);
    }
    __syncthreads();

    u64 acc[4][2];
#pragma unroll
    for (int i = 0; i < 4; ++i) { acc[i][0] = 0ULL; acc[i][1] = 0ULL; }

#pragma unroll 4
    for (int kk = 0; kk < 16; ++kk) {
        int sw  = (kk & 7) << 2;
        int r0s = r0 ^ sw;
        int c0s = c0 ^ sw;
#pragma unroll
        for (int j = 0; j < 4; ++j) {
            int k = kk * 4 + j;
            float4 a = *(const float4*)&xs[k][r0s];
            ulonglong2 b = *(const ulonglong2*)&ws[k][c0s];
            u64 a0 = pk2(a.x, a.x), a1 = pk2(a.y, a.y);
            u64 a2 = pk2(a.z, a.z), a3 = pk2(a.w, a.w);
            fma2(acc[0][0], a0, b.x); fma2(acc[0][1], a0, b.y);
            fma2(acc[1][0], a1, b.x); fma2(acc[1][1], a1, b.y);
            fma2(acc[2][0], a2, b.x); fma2(acc[2][1], a2, b.y);
            fma2(acc[3][0], a3, b.x); fma2(acc[3][1], a3, b.y);
        }
    }
    __syncthreads();
#pragma unroll
    for (int l = 0; l < 4; ++l) {
        int row = (srow + l * 16) ^ ssw;
        xs[skq * 4 + 0][row] = xv[l].x; xs[skq * 4 + 1][row] = xv[l].y;
        xs[skq * 4 + 2][row] = xv[l].z; xs[skq * 4 + 3][row] = xv[l].w;
        ws[skq * 4 + 0][row] = wv[l].x; ws[skq * 4 + 1][row] = wv[l].y;
        ws[skq * 4 + 2][row] = wv[l].z; ws[skq * 4 + 3][row] = wv[l].w;
    }
    __syncthreads();
#pragma unroll 4
    for (int kk = 0; kk < 16; ++kk) {
        int sw  = (kk & 7) << 2;
        int r0s = r0 ^ sw;
        int c0s = c0 ^ sw;
#pragma unroll
        for (int j = 0; j < 4; ++j) {
            int k = kk * 4 + j;
            float4 a = *(const float4*)&xs[k][r0s];
            ulonglong2 b = *(const ulonglong2*)&ws[k][c0s];
            u64 a0 = pk2(a.x, a.x), a1 = pk2(a.y, a.y);
            u64 a2 = pk2(a.z, a.z), a3 = pk2(a.w, a.w);
            fma2(acc[0][0], a0, b.x); fma2(acc[0][1], a0, b.y);
            fma2(acc[1][0], a1, b.x); fma2(acc[1][1], a1, b.y);
            fma2(acc[2][0], a2, b.x); fma2(acc[2][1], a2, b.y);
            fma2(acc[3][0], a3, b.x); fma2(acc[3][1], a3, b.y);
        }
    }

    float4 bb = *(const float4*)(bih + bn * 64 + c0);
#pragma unroll
    for (int i = 0; i < 4; ++i) {
        float4 o;
        up2(acc[i][0], o.x, o.y);
        up2(acc[i][1], o.z, o.w);
        o.x += bb.x; o.y += bb.y; o.z += bb.z; o.w += bb.w;
        *(float4*)(g_xg + (size_t)(bm * 64 + r0 + i) * GG + bn * 64 + c0) = o;
    }
}

// ---------------------------------------------------------------------------
// Phase 2: mma.sync (HMMA) bf16-split recurrence. 32 clusters x 4 CTAs,
// 384 threads = 12 warps, warp w owns gate rows [16w, 16w+16).
// hg[192][8] = W[192][256] @ h[256][8]: per warp 16 k-tiles x 3 passes of
// m16n8k16 (W1*hHi + W1*hLo + W2*hHi). W1 frags resident in registers.
// h in SMEM as bf16 hi/lo rows: [phase][k][2 x 16B], bank-swizzled.
// ---------------------------------------------------------------------------
#define TPB2 384

#define OFF_W2   0                        // 12*16*32*16 = 98304
#define OFF_HSM  98304                    // 2*256*32    = 16384
#define OFF_PS   (98304 + 16384)          // 192*8*4     = 6144
#define OFF_BSM  (OFF_PS + 6144)          // 768
#define OFF_HLOC (OFF_BSM + 768)          // 2*64*8*4    = 4096
#define SM2_BYTES (OFF_HLOC + 4096)       // 125696

__device__ __forceinline__ uint32_t pkbf(float x, float y) {
    __nv_bfloat162 h = __floats2bfloat162_rn(x, y);
    return *(uint32_t*)&h;
}
__device__ __forceinline__ float bfres(float x) {   // x - bf16(x)
    return x - __bfloat162float(__float2bfloat16(x));
}
__device__ __forceinline__ void ldsm_x2t(uint32_t& r0, uint32_t& r1, uint32_t a) {
    asm volatile("ldmatrix.sync.aligned.m8n8.x2.trans.shared.b16 {%0,%1}, [%2];"
                 : "=r"(r0), "=r"(r1) : "r"(a));
}
__device__ __forceinline__ void mma16816(float& c0, float& c1, float& c2, float& c3,
                                         uint32_t a0, uint32_t a1, uint32_t a2, uint32_t a3,
                                         uint32_t b0, uint32_t b1) {
    asm("mma.sync.aligned.m16n8k16.row.col.f32.bf16.bf16.f32 "
        "{%0,%1,%2,%3}, {%4,%5,%6,%7}, {%8,%9}, {%0,%1,%2,%3};"
        : "+f"(c0), "+f"(c1), "+f"(c2), "+f"(c3)
        : "r"(a0), "r"(a1), "r"(a2), "r"(a3), "r"(b0), "r"(b1));
}

__global__ __launch_bounds__(TPB2, 1) __cluster_dims__(4, 1, 1)
void gru_seq_mma(const float* __restrict__ Whh,
                 const float* __restrict__ bhh,
                 float* __restrict__ out)
{
    extern __shared__ char smem[];
    const uint32_t smb = (uint32_t)__cvta_generic_to_shared(smem);
    float* ps   = (float*)(smem + OFF_PS);
    float* bsm  = (float*)(smem + OFF_BSM);
    float* hloc = (float*)(smem + OFF_HLOC);

    const int tid  = threadIdx.x;
    const int wid  = tid >> 5;
    const int lane = tid & 31;
    const int gq   = lane >> 2;       // mma group 0..7
    const int tq   = lane & 3;        // mma thread-in-group
    uint32_t srank;
    asm("mov.u32 %0, %%cluster_ctarank;" : "=r"(srank));
    const int s = (int)srank;
    const int g = blockIdx.x >> 2;

    // ---- init: W fragments (W1 -> regs, W2 -> smem), biases, zero h ----
    uint32_t w1f[16][4];
    {
        const int r0g = ((wid * 16 + gq) >> 6 << 8) + (s << 6) + ((wid * 16 + gq) & 63);
        const int r1g = ((wid * 16 + gq + 8) >> 6 << 8) + (s << 6) + ((wid * 16 + gq + 8) & 63);
        const float* W0 = Whh + (size_t)r0g * 256;
        const float* W1 = Whh + (size_t)r1g * 256;
#pragma unroll
        for (int kt = 0; kt < 16; ++kt) {
            int c0 = kt * 16 + tq * 2;
            float w00 = W0[c0],     w01 = W0[c0 + 1];
            float w10 = W1[c0],     w11 = W1[c0 + 1];
            float w02 = W0[c0 + 8], w03 = W0[c0 + 9];
            float w12 = W1[c0 + 8], w13 = W1[c0 + 9];
            w1f[kt][0] = pkbf(w00, w01);
            w1f[kt][1] = pkbf(w10, w11);
            w1f[kt][2] = pkbf(w02, w03);
            w1f[kt][3] = pkbf(w12, w13);
            uint4 w2;
            w2.x = pkbf(bfres(w00), bfres(w01));
            w2.y = pkbf(bfres(w10), bfres(w11));
            w2.z = pkbf(bfres(w02), bfres(w03));
            w2.w = pkbf(bfres(w12), bfres(w13));
            *(uint4*)(smem + OFF_W2 + (((wid * 16 + kt) * 32) + lane) * 16) = w2;
        }
    }
    if (tid < 192) {
        int grow = ((tid >> 6) << 8) + (s << 6) + (tid & 63);
        bsm[tid] = bhh[grow];
    }
    for (int i = tid; i < (16384 + 4096) / 4; i += TPB2) {
        if (i < 16384 / 4) ((float*)(smem + OFF_HSM))[i] = 0.f;
        else hloc[i - 16384 / 4] = 0.f;
    }
    __syncthreads();
    asm volatile("barrier.cluster.arrive.aligned;" ::: "memory");
    asm volatile("barrier.cluster.wait.aligned;" ::: "memory");

    const int jj = tid >> 2;          // gate j 0..63 (tid<256)
    const int bq = (tid & 3) * 2;     // gate batch pair
    const int kln = lane & 15;        // ldmatrix source row lane

    // per-thread gate biases
    float br = 0.f, bz = 0.f, bn_ = 0.f;
    if (tid < 256) { br = bsm[jj]; bz = bsm[64 + jj]; bn_ = bsm[128 + jj]; }

    // push base offsets (k = s*64 + jj)
    const int pk = (s << 6) + jj;
    const uint32_t push_hi_off = (uint32_t)(OFF_HSM + pk * 32 + (((pk >> 2) & 1) << 4) + bq * 2);

    for (int t = 0; t < TT; ++t) {
        const int p = t & 1;

        // xg prefetch (DRAM latency hidden under GEMM)
        float xr0, xz0, xn0, xr1, xz1, xn1;
        if (tid < 256) {
            size_t base = ((size_t)(g * 8 + bq) * TT + t) * GG + (s << 6) + jj;
            xr0 = g_xg[base];          xz0 = g_xg[base + 256];
            xn0 = g_xg[base + 512];
            xr1 = g_xg[base + (size_t)TT * GG];
            xz1 = g_xg[base + (size_t)TT * GG + 256];
            xn1 = g_xg[base + (size_t)TT * GG + 512];
        }

        // ---- GEMM: 16 k-tiles x (W1*hHi + W1*hLo + W2*hHi) ----
        float c0 = 0.f, c1 = 0.f, c2 = 0.f, c3 = 0.f;
        {
            const uint32_t hbase = smb + (uint32_t)(OFF_HSM + p * 8192);
            const char* w2p = smem + OFF_W2 + (size_t)wid * 16 * 512 + lane * 16;
#pragma unroll
            for (int kt = 0; kt < 16; ++kt) {
                int k0 = kt * 16 + kln;
                uint32_t rowHi = hbase + (uint32_t)(k0 * 32 + (((k0 >> 2) & 1) << 4));
                uint32_t rowLo = rowHi ^ 16u;
                uint32_t bh0, bh1, bl0, bl1;
                ldsm_x2t(bh0, bh1, rowHi);
                ldsm_x2t(bl0, bl1, rowLo);
                uint4 w2 = *(const uint4*)(w2p + kt * 512);
                mma16816(c0, c1, c2, c3,
                         w1f[kt][0], w1f[kt][1], w1f[kt][2], w1f[kt][3], bh0, bh1);
                mma16816(c0, c1, c2, c3,
                         w1f[kt][0], w1f[kt][1], w1f[kt][2], w1f[kt][3], bl0, bl1);
                mma16816(c0, c1, c2, c3, w2.x, w2.y, w2.z, w2.w, bh0, bh1);
            }
        }
        // deposit D: rows wid*16+gq and +8, cols tq*2, tq*2+1
        *(float2*)(ps + (wid * 16 + gq) * 8 + tq * 2)     = make_float2(c0, c1);
        *(float2*)(ps + (wid * 16 + gq + 8) * 8 + tq * 2) = make_float2(c2, c3);
        __syncthreads();

        // ---- gates: 256 threads x (1 j, 2 batches) ----
        if (tid < 256) {
            float2 hr = *(const float2*)(ps + jj * 8 + bq);
            float2 hz = *(const float2*)(ps + (64 + jj) * 8 + bq);
            float2 hn = *(const float2*)(ps + (128 + jj) * 8 + bq);
            float2 ho = *(const float2*)(hloc + p * 512 + jj * 8 + bq);

            float r0g = __fdividef(1.f, 1.f + __expf(-(xr0 + hr.x + br)));
            float z0g = __fdividef(1.f, 1.f + __expf(-(xz0 + hz.x + bz)));
            float v0  = xn0 + r0g * (hn.x + bn_);
            float n0  = 1.f - 2.f * __fdividef(1.f, __expf(2.f * v0) + 1.f);
            float hw0 = (1.f - z0g) * n0 + z0g * ho.x;

            float r1g = __fdividef(1.f, 1.f + __expf(-(xr1 + hr.y + br)));
            float z1g = __fdividef(1.f, 1.f + __expf(-(xz1 + hz.y + bz)));
            float v1  = xn1 + r1g * (hn.y + bn_);
            float n1  = 1.f - 2.f * __fdividef(1.f, __expf(2.f * v1) + 1.f);
            float hw1 = (1.f - z1g) * n1 + z1g * ho.y;

            uint32_t hiw = pkbf(hw0, hw1);
            uint32_t low = pkbf(bfres(hw0), bfres(hw1));

            uint32_t hiA = smb + push_hi_off + (uint32_t)((1 - p) * 8192);
            uint32_t loA = hiA ^ 16u;
#pragma unroll
            for (int rk = 0; rk < 4; ++rk) {
                uint32_t ra, rb;
                asm volatile("mapa.shared::cluster.u32 %0, %1, %2;"
                             : "=r"(ra) : "r"(hiA), "r"(rk));
                asm volatile("mapa.shared::cluster.u32 %0, %1, %2;"
                             : "=r"(rb) : "r"(loA), "r"(rk));
                asm volatile("st.shared::cluster.b32 [%0], %1;"
                             :: "r"(ra), "r"(hiw) : "memory");
                asm volatile("st.shared::cluster.b32 [%0], %1;"
                             :: "r"(rb), "r"(low) : "memory");
            }

            size_t ob = ((size_t)(g * 8 + bq) * TT + t) * HH + (s << 6) + jj;
            out[ob] = hw0;
            out[ob + (size_t)TT * HH] = hw1;
            *(float2*)(hloc + (1 - p) * 512 + jj * 8 + bq) = make_float2(hw0, hw1);
        }
        asm volatile("barrier.cluster.arrive.aligned;" ::: "memory");
        asm volatile("barrier.cluster.wait.aligned;" ::: "memory");
    }
}

// ---------------------------------------------------------------------------
extern "C" void kernel_launch(void* const* d_in, const int* in_sizes, int n_in,
                              void* d_out, int out_size)
{
    const float* x   = (const float*)d_in[0];
    const float* Wih = (const float*)d_in[1];
    const float* Whh = (const float*)d_in[2];
    const float* bih = (const float*)d_in[3];
    const float* bhh = (const float*)d_in[4];
    float* out = (float*)d_out;

    cudaFuncSetAttribute(gru_seq_mma,
                         cudaFuncAttributeMaxDynamicSharedMemorySize, SM2_BYTES);

    dim3 g1(BB * TT / 64, GG / 64);
    xg_gemm_kernel<<<g1, 256>>>(x, Wih, bih);
    gru_seq_mma<<<128, TPB2, SM2_BYTES>>>(Whh, bhh, out);
}

// round 9
// speedup vs baseline: 2.4269x; 1.2430x over previous
#include <cuda_runtime.h>
#include <cuda_bf16.h>
#include <cstdint>
#include <cstddef>

#define BB 256
#define TT 512
#define II 128
#define HH 256
#define GG 768

typedef unsigned long long u64;

__device__ float g_xg[(size_t)BB * TT * GG];

// ---------------- bf16 helpers ----------------
__device__ __forceinline__ uint32_t pkbf(float x, float y) {
    __nv_bfloat162 h = __floats2bfloat162_rn(x, y);
    return *(uint32_t*)&h;
}
__device__ __forceinline__ float bfres(float x) {   // x - bf16(x)
    return x - __bfloat162float(__float2bfloat16(x));
}
__device__ __forceinline__ void ldsm_x4(uint32_t& r0, uint32_t& r1,
                                        uint32_t& r2, uint32_t& r3, uint32_t a) {
    asm volatile("ldmatrix.sync.aligned.m8n8.x4.shared.b16 {%0,%1,%2,%3}, [%4];"
                 : "=r"(r0), "=r"(r1), "=r"(r2), "=r"(r3) : "r"(a));
}
__device__ __forceinline__ void ldsm_x2t(uint32_t& r0, uint32_t& r1, uint32_t a) {
    asm volatile("ldmatrix.sync.aligned.m8n8.x2.trans.shared.b16 {%0,%1}, [%2];"
                 : "=r"(r0), "=r"(r1) : "r"(a));
}
__device__ __forceinline__ void mma16816(float& c0, float& c1, float& c2, float& c3,
                                         uint32_t a0, uint32_t a1, uint32_t a2, uint32_t a3,
                                         uint32_t b0, uint32_t b1) {
    asm("mma.sync.aligned.m16n8k16.row.col.f32.bf16.bf16.f32 "
        "{%0,%1,%2,%3}, {%4,%5,%6,%7}, {%8,%9}, {%0,%1,%2,%3};"
        : "+f"(c0), "+f"(c1), "+f"(c2), "+f"(c3)
        : "r"(a0), "r"(a1), "r"(a2), "r"(a3), "r"(b0), "r"(b1));
}

// ---------------------------------------------------------------------------
// Phase 1 (HMMA bf16-split): xg = x @ W_ih^T + b_ih
// Tiles: 128(M) x 64(N) x 128(K). 256 thr = 8 warps (4m x 2n), each warp
// 32 rows x 32 cols. 3-pass split: xHi*wHi + xHi*wLo + xLo*wHi.
// SMEM: A hi/lo 32KB each, B hi/lo 16KB each = 96KB -> 2 CTAs/SM.
// Layout: row r at r*256B; chunk c (8 bf16) at ((c ^ (r&7))<<4).
// ---------------------------------------------------------------------------
#define SM1_AHI 0
#define SM1_ALO 32768
#define SM1_BHI 65536
#define SM1_BLO 81920
#define SM1_BYTES 98304

__global__ __launch_bounds__(256, 2) void xg_mma_kernel(
    const float* __restrict__ x,
    const float* __restrict__ Wih,
    const float* __restrict__ bih)
{
    extern __shared__ char sm1[];
    const uint32_t smb = (uint32_t)__cvta_generic_to_shared(sm1);
    const int tid  = threadIdx.x;
    const int warp = tid >> 5;
    const int lane = tid & 31;
    const int bn = blockIdx.x;        // 0..11  (N tiles, fast -> L2 reuse of x)
    const int bm = blockIdx.y;        // 0..1023

    // ---- stage A (x tile 128x128 fp32 -> bf16 hi/lo, swizzled) ----
    {
        const float* xr = x + (size_t)bm * 128 * II;
        const int r_ = tid >> 5, kq = tid & 31;
        const uint32_t off0 = (uint32_t)((((kq >> 1) ^ (r_ & 7)) << 4) + (kq & 1) * 8);
#pragma unroll
        for (int i = 0; i < 16; ++i) {
            int r = r_ + i * 8;
            float4 v = *(const float4*)(xr + (size_t)r * II + kq * 4);
            uint2 hi = make_uint2(pkbf(v.x, v.y), pkbf(v.z, v.w));
            uint2 lo = make_uint2(pkbf(bfres(v.x), bfres(v.y)),
                                  pkbf(bfres(v.z), bfres(v.w)));
            uint32_t off = (uint32_t)(r * 256) + off0;
            *(uint2*)(sm1 + SM1_AHI + off) = hi;
            *(uint2*)(sm1 + SM1_ALO + off) = lo;
        }
        // ---- stage B (W tile 64x128) ----
        const float* wr = Wih + (size_t)bn * 64 * II;
#pragma unroll
        for (int i = 0; i < 8; ++i) {
            int n = r_ + i * 8;
            float4 v = *(const float4*)(wr + (size_t)n * II + kq * 4);
            uint2 hi = make_uint2(pkbf(v.x, v.y), pkbf(v.z, v.w));
            uint2 lo = make_uint2(pkbf(bfres(v.x), bfres(v.y)),
                                  pkbf(bfres(v.z), bfres(v.w)));
            uint32_t off = (uint32_t)(n * 256) + off0;
            *(uint2*)(sm1 + SM1_BHI + off) = hi;
            *(uint2*)(sm1 + SM1_BLO + off) = lo;
        }
    }
    __syncthreads();

    // ---- compute ----
    const int mr2 = warp >> 1;        // m sub-tile 0..3 (32 rows)
    const int nc2 = warp & 1;         // n sub-tile 0..1 (32 cols)
    const uint32_t lrow  = (uint32_t)(lane & 15);
    const uint32_t khalf = (uint32_t)(lane >> 4);
    const uint32_t r7    = lrow & 7u;
    const uint32_t aRB = smb + SM1_AHI + (uint32_t)(mr2 * 32 + lrow) * 256u;
    const uint32_t bRB = smb + SM1_BHI + (uint32_t)(nc2 * 32 + lrow) * 256u;

    float c[2][4][4];
#pragma unroll
    for (int m = 0; m < 2; ++m)
#pragma unroll
        for (int n = 0; n < 4; ++n)
#pragma unroll
            for (int q = 0; q < 4; ++q) c[m][n][q] = 0.f;

#pragma unroll
    for (int kt = 0; kt < 8; ++kt) {
        const uint32_t swz = (((uint32_t)(kt * 2) + khalf) ^ r7) << 4;
        uint32_t ah[2][4], al[2][4], bh[2][4], bl[2][4];
#pragma unroll
        for (int m = 0; m < 2; ++m) {
            uint32_t a = aRB + (uint32_t)(m * 4096) + swz;
            ldsm_x4(ah[m][0], ah[m][1], ah[m][2], ah[m][3], a);
            ldsm_x4(al[m][0], al[m][1], al[m][2], al[m][3], a + 32768u);
        }
#pragma unroll
        for (int nn = 0; nn < 2; ++nn) {
            uint32_t b = bRB + (uint32_t)(nn * 4096) + swz;
            ldsm_x4(bh[nn][0], bh[nn][1], bh[nn][2], bh[nn][3], b);
            ldsm_x4(bl[nn][0], bl[nn][1], bl[nn][2], bl[nn][3], b + 16384u);
        }
#pragma unroll
        for (int m = 0; m < 2; ++m) {
#pragma unroll
            for (int nn = 0; nn < 2; ++nn) {
                float* c0 = c[m][nn * 2];
                float* c1 = c[m][nn * 2 + 1];
                // pass 1: hi*hi
                mma16816(c0[0], c0[1], c0[2], c0[3],
                         ah[m][0], ah[m][1], ah[m][2], ah[m][3],
                         bh[nn][0], bh[nn][2]);
                mma16816(c1[0], c1[1], c1[2], c1[3],
                         ah[m][0], ah[m][1], ah[m][2], ah[m][3],
                         bh[nn][1], bh[nn][3]);
                // pass 2: hi*lo
                mma16816(c0[0], c0[1], c0[2], c0[3],
                         ah[m][0], ah[m][1], ah[m][2], ah[m][3],
                         bl[nn][0], bl[nn][2]);
                mma16816(c1[0], c1[1], c1[2], c1[3],
                         ah[m][0], ah[m][1], ah[m][2], ah[m][3],
                         bl[nn][1], bl[nn][3]);
                // pass 3: lo*hi
                mma16816(c0[0], c0[1], c0[2], c0[3],
                         al[m][0], al[m][1], al[m][2], al[m][3],
                         bh[nn][0], bh[nn][2]);
                mma16816(c1[0], c1[1], c1[2], c1[3],
                         al[m][0], al[m][1], al[m][2], al[m][3],
                         bh[nn][1], bh[nn][3]);
            }
        }
    }

    // ---- epilogue: add bias, store fp32 ----
    const int gq = lane >> 2, tq = lane & 3;
#pragma unroll
    for (int nf = 0; nf < 4; ++nf) {
        int col = bn * 64 + nc2 * 32 + nf * 8 + tq * 2;
        float2 bb = *(const float2*)(bih + col);
#pragma unroll
        for (int m = 0; m < 2; ++m) {
            int row = bm * 128 + mr2 * 32 + m * 16 + gq;
            float2 o0 = make_float2(c[m][nf][0] + bb.x, c[m][nf][1] + bb.y);
            float2 o1 = make_float2(c[m][nf][2] + bb.x, c[m][nf][3] + bb.y);
            *(float2*)(g_xg + (size_t)row * GG + col) = o0;
            *(float2*)(g_xg + (size_t)(row + 8) * GG + col) = o1;
        }
    }
}

// ---------------------------------------------------------------------------
// Phase 2 (R8, frozen): mma.sync bf16-split recurrence. 32 clusters x 4 CTAs.
// ---------------------------------------------------------------------------
#define TPB2 384

#define OFF_W2   0
#define OFF_HSM  98304
#define OFF_PS   (98304 + 16384)
#define OFF_BSM  (OFF_PS + 6144)
#define OFF_HLOC (OFF_BSM + 768)
#define SM2_BYTES (OFF_HLOC + 4096)

__global__ __launch_bounds__(TPB2, 1) __cluster_dims__(4, 1, 1)
void gru_seq_mma(const float* __restrict__ Whh,
                 const float* __restrict__ bhh,
                 float* __restrict__ out)
{
    extern __shared__ char smem[];
    const uint32_t smb = (uint32_t)__cvta_generic_to_shared(smem);
    float* ps   = (float*)(smem + OFF_PS);
    float* bsm  = (float*)(smem + OFF_BSM);
    float* hloc = (float*)(smem + OFF_HLOC);

    const int tid  = threadIdx.x;
    const int wid  = tid >> 5;
    const int lane = tid & 31;
    const int gq   = lane >> 2;
    const int tq   = lane & 3;
    uint32_t srank;
    asm("mov.u32 %0, %%cluster_ctarank;" : "=r"(srank));
    const int s = (int)srank;
    const int g = blockIdx.x >> 2;

    uint32_t w1f[16][4];
    {
        const int r0g = ((wid * 16 + gq) >> 6 << 8) + (s << 6) + ((wid * 16 + gq) & 63);
        const int r1g = ((wid * 16 + gq + 8) >> 6 << 8) + (s << 6) + ((wid * 16 + gq + 8) & 63);
        const float* W0 = Whh + (size_t)r0g * 256;
        const float* W1 = Whh + (size_t)r1g * 256;
#pragma unroll
        for (int kt = 0; kt < 16; ++kt) {
            int c0 = kt * 16 + tq * 2;
            float w00 = W0[c0],     w01 = W0[c0 + 1];
            float w10 = W1[c0],     w11 = W1[c0 + 1];
            float w02 = W0[c0 + 8], w03 = W0[c0 + 9];
            float w12 = W1[c0 + 8], w13 = W1[c0 + 9];
            w1f[kt][0] = pkbf(w00, w01);
            w1f[kt][1] = pkbf(w10, w11);
            w1f[kt][2] = pkbf(w02, w03);
            w1f[kt][3] = pkbf(w12, w13);
            uint4 w2;
            w2.x = pkbf(bfres(w00), bfres(w01));
            w2.y = pkbf(bfres(w10), bfres(w11));
            w2.z = pkbf(bfres(w02), bfres(w03));
            w2.w = pkbf(bfres(w12), bfres(w13));
            *(uint4*)(smem + OFF_W2 + (((wid * 16 + kt) * 32) + lane) * 16) = w2;
        }
    }
    if (tid < 192) {
        int grow = ((tid >> 6) << 8) + (s << 6) + (tid & 63);
        bsm[tid] = bhh[grow];
    }
    for (int i = tid; i < (16384 + 4096) / 4; i += TPB2) {
        if (i < 16384 / 4) ((float*)(smem + OFF_HSM))[i] = 0.f;
        else hloc[i - 16384 / 4] = 0.f;
    }
    __syncthreads();
    asm volatile("barrier.cluster.arrive.aligned;" ::: "memory");
    asm volatile("barrier.cluster.wait.aligned;" ::: "memory");

    const int jj = tid >> 2;
    const int bq = (tid & 3) * 2;
    const int kln = lane & 15;

    float br = 0.f, bz = 0.f, bn_ = 0.f;
    if (tid < 256) { br = bsm[jj]; bz = bsm[64 + jj]; bn_ = bsm[128 + jj]; }

    const int pk = (s << 6) + jj;
    const uint32_t push_hi_off = (uint32_t)(OFF_HSM + pk * 32 + (((pk >> 2) & 1) << 4) + bq * 2);

    for (int t = 0; t < TT; ++t) {
        const int p = t & 1;

        float xr0, xz0, xn0, xr1, xz1, xn1;
        if (tid < 256) {
            size_t base = ((size_t)(g * 8 + bq) * TT + t) * GG + (s << 6) + jj;
            xr0 = g_xg[base];          xz0 = g_xg[base + 256];
            xn0 = g_xg[base + 512];
            xr1 = g_xg[base + (size_t)TT * GG];
            xz1 = g_xg[base + (size_t)TT * GG + 256];
            xn1 = g_xg[base + (size_t)TT * GG + 512];
        }

        float c0 = 0.f, c1 = 0.f, c2 = 0.f, c3 = 0.f;
        {
            const uint32_t hbase = smb + (uint32_t)(OFF_HSM + p * 8192);
            const char* w2p = smem + OFF_W2 + (size_t)wid * 16 * 512 + lane * 16;
#pragma unroll
            for (int kt = 0; kt < 16; ++kt) {
                int k0 = kt * 16 + kln;
                uint32_t rowHi = hbase + (uint32_t)(k0 * 32 + (((k0 >> 2) & 1) << 4));
                uint32_t rowLo = rowHi ^ 16u;
                uint32_t bh0, bh1, bl0, bl1;
                ldsm_x2t(bh0, bh1, rowHi);
                ldsm_x2t(bl0, bl1, rowLo);
                uint4 w2 = *(const uint4*)(w2p + kt * 512);
                mma16816(c0, c1, c2, c3,
                         w1f[kt][0], w1f[kt][1], w1f[kt][2], w1f[kt][3], bh0, bh1);
                mma16816(c0, c1, c2, c3,
                         w1f[kt][0], w1f[kt][1], w1f[kt][2], w1f[kt][3], bl0, bl1);
                mma16816(c0, c1, c2, c3, w2.x, w2.y, w2.z, w2.w, bh0, bh1);
            }
        }
        *(float2*)(ps + (wid * 16 + gq) * 8 + tq * 2)     = make_float2(c0, c1);
        *(float2*)(ps + (wid * 16 + gq + 8) * 8 + tq * 2) = make_float2(c2, c3);
        __syncthreads();

        if (tid < 256) {
            float2 hr = *(const float2*)(ps + jj * 8 + bq);
            float2 hz = *(const float2*)(ps + (64 + jj) * 8 + bq);
            float2 hn = *(const float2*)(ps + (128 + jj) * 8 + bq);
            float2 ho = *(const float2*)(hloc + p * 512 + jj * 8 + bq);

            float r0g = __fdividef(1.f, 1.f + __expf(-(xr0 + hr.x + br)));
            float z0g = __fdividef(1.f, 1.f + __expf(-(xz0 + hz.x + bz)));
            float v0  = xn0 + r0g * (hn.x + bn_);
            float n0  = 1.f - 2.f * __fdividef(1.f, __expf(2.f * v0) + 1.f);
            float hw0 = (1.f - z0g) * n0 + z0g * ho.x;

            float r1g = __fdividef(1.f, 1.f + __expf(-(xr1 + hr.y + br)));
            float z1g = __fdividef(1.f, 1.f + __expf(-(xz1 + hz.y + bz)));
            float v1  = xn1 + r1g * (hn.y + bn_);
            float n1  = 1.f - 2.f * __fdividef(1.f, __expf(2.f * v1) + 1.f);
            float hw1 = (1.f - z1g) * n1 + z1g * ho.y;

            uint32_t hiw = pkbf(hw0, hw1);
            uint32_t low = pkbf(bfres(hw0), bfres(hw1));

            uint32_t hiA = smb + push_hi_off + (uint32_t)((1 - p) * 8192);
            uint32_t loA = hiA ^ 16u;
#pragma unroll
            for (int rk = 0; rk < 4; ++rk) {
                uint32_t ra, rb;
                asm volatile("mapa.shared::cluster.u32 %0, %1, %2;"
                             : "=r"(ra) : "r"(hiA), "r"(rk));
                asm volatile("mapa.shared::cluster.u32 %0, %1, %2;"
                             : "=r"(rb) : "r"(loA), "r"(rk));
                asm volatile("st.shared::cluster.b32 [%0], %1;"
                             :: "r"(ra), "r"(hiw) : "memory");
                asm volatile("st.shared::cluster.b32 [%0], %1;"
                             :: "r"(rb), "r"(low) : "memory");
            }

            size_t ob = ((size_t)(g * 8 + bq) * TT + t) * HH + (s << 6) + jj;
            out[ob] = hw0;
            out[ob + (size_t)TT * HH] = hw1;
            *(float2*)(hloc + (1 - p) * 512 + jj * 8 + bq) = make_float2(hw0, hw1);
        }
        asm volatile("barrier.cluster.arrive.aligned;" ::: "memory");
        asm volatile("barrier.cluster.wait.aligned;" ::: "memory");
    }
}

// ---------------------------------------------------------------------------
extern "C" void kernel_launch(void* const* d_in, const int* in_sizes, int n_in,
                              void* d_out, int out_size)
{
    const float* x   = (const float*)d_in[0];
    const float* Wih = (const float*)d_in[1];
    const float* Whh = (const float*)d_in[2];
    const float* bih = (const float*)d_in[3];
    const float* bhh = (const float*)d_in[4];
    float* out = (float*)d_out;

    cudaFuncSetAttribute(xg_mma_kernel,
                         cudaFuncAttributeMaxDynamicSharedMemorySize, SM1_BYTES);
    cudaFuncSetAttribute(gru_seq_mma,
                         cudaFuncAttributeMaxDynamicSharedMemorySize, SM2_BYTES);

    dim3 g1(GG / 64, BB * TT / 128);   // (bn=12, bm=1024)
    xg_mma_kernel<<<g1, 256, SM1_BYTES>>>(x, Wih, bih);
    gru_seq_mma<<<128, TPB2, SM2_BYTES>>>(Whh, bhh, out);
}